// round 11
// baseline (speedup 1.0000x reference)
#include <cuda_runtime.h>
#include <math.h>
#include <stdint.h>

#define Bsz   64
#define Tlen  512
#define HID   512
#define G4    2048
#define CTX   792
#define IND   1048
#define BCL   8
#define VOC   260
#define PBL   (Tlen + BCL)   // 520
#define PJ    (BCL * VOC)    // 2080
#define WP    516            // padded W row stride (mod 32 == 4 -> conflict-free)
#define HP    68             // padded h-chunk row stride
#define GRIDR 128            // blocks per layer
#define UPB   4              // hidden units per block
#define NCH   8              // h chunks per step (64 units each)
#define CKS   32             // counter padding stride (128B line each)

// ---------------- device scratch ------------------------------------------
__device__ float g_ctxT[CTX * Bsz];
__device__ int   g_pb[Bsz * PBL];
__device__ float g_gctx0[G4 * Bsz];
__device__ float g_PT[(size_t)PJ * G4];
__device__ float g_gx[(size_t)Tlen * G4 * Bsz];       // layer-0 gate preact [t][g][b]
__device__ float g_h0r[2][Bsz * HID];                 // layer-0 h ring
__device__ float g_h1r[2][Bsz * HID];                 // layer-1 h ring
__device__ float g_h1[(size_t)Tlen * Bsz * HID];      // layer-0 outputs [t][b][k]
__device__ float g_h2[(size_t)Tlen * Bsz * HID];      // layer-1 outputs
__device__ unsigned g_ck0[Tlen * NCH * CKS];          // padded chunk counters L0
__device__ unsigned g_ck1[Tlen * NCH * CKS];          // padded chunk counters L1

// ---------------- helpers --------------------------------------------------
__device__ __forceinline__ void fma2(unsigned long long& acc,
                                     unsigned long long a, unsigned long long b) {
    asm("fma.rn.f32x2 %0, %1, %2, %0;" : "+l"(acc) : "l"(a), "l"(b));
}
__device__ __forceinline__ float usum(unsigned long long v) {
    float lo = __uint_as_float((unsigned)(v & 0xffffffffull));
    float hi = __uint_as_float((unsigned)(v >> 32));
    return lo + hi;
}
__device__ __forceinline__ float sigf(float x) {
    return __fdividef(1.f, 1.f + __expf(-x));
}
__device__ __forceinline__ float tanh_fast(float x) {
    return __fmaf_rn(2.f, sigf(2.f * x), -1.f);
}
__device__ __forceinline__ void cpasync16(uint32_t s, const void* g) {
    asm volatile("cp.async.cg.shared.global [%0], [%1], 16;" :: "r"(s), "l"(g));
}
__device__ __forceinline__ void waitcnt16(const unsigned* p) {
    unsigned v;
    do {
        asm volatile("ld.acquire.gpu.global.u32 %0, [%1];" : "=r"(v) : "l"(p));
    } while (v < 16u);
}
__device__ __forceinline__ void signal_chunk(unsigned* p) {
    asm volatile("red.release.gpu.global.add.u32 [%0], %1;" :: "l"(p), "r"(1u) : "memory");
}

struct StreamCtx {
    uint32_t sdst[2][4];
    int sb[4], sk[4];
};

// Chunk-streamed GEMM: 8 chunks of 64 k, each gated by a padded counter,
// cp.async double-buffered. Accumulates into a0/a1.
__device__ __forceinline__ void gemm_stream(
    const float4* __restrict__ src, const unsigned* __restrict__ ckt,
    float* __restrict__ hbuf0, float* __restrict__ hbuf1,
    const StreamCtx& sc, const float* const* wp_, int b, int tid,
    unsigned long long* a0, unsigned long long* a1)
{
    if (tid == 0) waitcnt16(ckt);
    __syncthreads();
#pragma unroll
    for (int n = 0; n < 4; n++)
        cpasync16(sc.sdst[0][n], src + sc.sb[n] * 128 + sc.sk[n]);
    asm volatile("cp.async.commit_group;");
    for (int c = 0; c < NCH; c++) {
        if (c < NCH - 1) {
            if (tid == 0) waitcnt16(ckt + (size_t)(c + 1) * CKS);
            __syncthreads();
            int nb = (c + 1) & 1;
#pragma unroll
            for (int n = 0; n < 4; n++)
                cpasync16(sc.sdst[nb][n], src + sc.sb[n] * 128 + (c + 1) * 16 + sc.sk[n]);
            asm volatile("cp.async.commit_group;");
            asm volatile("cp.async.wait_group 1;");
        } else {
            asm volatile("cp.async.wait_group 0;");
        }
        __syncthreads();
        const float* hb = (c & 1 ? hbuf1 : hbuf0) + b * HP;
#pragma unroll
        for (int kk = 0; kk < 64; kk += 4) {
            ulonglong2 h4 = *(const ulonglong2*)(hb + kk);
#pragma unroll
            for (int u = 0; u < UPB; u++) {
                ulonglong2 w4 = *(const ulonglong2*)(wp_[u] + c * 64 + kk);
                fma2(a0[u], h4.x, w4.x);
                fma2(a1[u], h4.y, w4.y);
            }
        }
    }
}

// ---------------- K0: context assembly (transposed) + byte stream ----------
__global__ void k_prep(const float* __restrict__ ecc, const int* __restrict__ cat,
                       const float* __restrict__ num, const int* __restrict__ pay,
                       const float* __restrict__ e0, const float* __restrict__ e1,
                       const float* __restrict__ e2) {
    int b = blockIdx.x;
    int c0 = cat[b * 3 + 0], c1 = cat[b * 3 + 1], c2 = cat[b * 3 + 2];
    for (int i = threadIdx.x; i < CTX; i += blockDim.x) {
        float v;
        if (i < 512)      v = ecc[b * 512 + i];
        else if (i < 562) v = e0[c0 * 50 + (i - 512)];
        else if (i < 626) v = e1[c1 * 64 + (i - 562)];
        else if (i < 776) v = e2[c2 * 150 + (i - 626)];
        else              v = num[b * 16 + (i - 776)];
        g_ctxT[i * Bsz + b] = v;
    }
    for (int p = threadIdx.x; p < PBL; p += blockDim.x) {
        int v = (p < BCL - 1) ? 256 : (p == BCL - 1 ? 257 : pay[b * Tlen + p - BCL]);
        g_pb[b * PBL + p] = v;
    }
}

// ---------------- K1: context gate projection ------------------------------
__global__ void k_gctx(const float* __restrict__ Wih0, const float* __restrict__ bih0,
                       const float* __restrict__ bhh0) {
    int g = blockIdx.x;
    int b = threadIdx.x;
    const float* w = Wih0 + (size_t)g * IND;
    float a0 = 0.f, a1 = 0.f, a2 = 0.f, a3 = 0.f;
    int k = 0;
    for (; k + 4 <= CTX; k += 4) {
        a0 += w[k]   * g_ctxT[k * Bsz + b];
        a1 += w[k+1] * g_ctxT[(k+1) * Bsz + b];
        a2 += w[k+2] * g_ctxT[(k+2) * Bsz + b];
        a3 += w[k+3] * g_ctxT[(k+3) * Bsz + b];
    }
    for (; k < CTX; k++) a0 += w[k] * g_ctxT[k * Bsz + b];
    g_gctx0[g * Bsz + b] = a0 + a1 + a2 + a3 + bih0[g] + bhh0[g];
}

// ---------------- K2: transposed byte-projection table ---------------------
__global__ void k_table(const float* __restrict__ Wih0, const float* __restrict__ be) {
    __shared__ float ws[BCL * 32];
    __shared__ float es[VOC * 33];
    int g = blockIdx.x, tid = threadIdx.x;
    if (tid < 256) ws[tid] = Wih0[(size_t)g * IND + CTX + tid];
    for (int i = tid; i < VOC * 32; i += blockDim.x) {
        int v = i >> 5, k = i & 31;
        es[v * 33 + k] = be[i];
    }
    __syncthreads();
    for (int idx = tid; idx < PJ; idx += blockDim.x) {
        int j = idx / VOC, v = idx - j * VOC;
        const float* w = ws + j * 32;
        const float* e = es + v * 33;
        float acc = 0.f;
#pragma unroll
        for (int k = 0; k < 32; k++) acc += w[k] * e[k];
        g_PT[(size_t)idx * G4 + g] = acc;
    }
}

// ---------------- K3: layer-0 input preactivation gx0[t][g][b] -------------
__global__ void __launch_bounds__(256) k_gx0() {
    __shared__ int pbs[BCL * Bsz];
    __shared__ float os[128 * 65];
    int g0 = blockIdx.x * 128;
    int t  = blockIdx.y;
    int tid = threadIdx.x;
    for (int i = tid; i < BCL * Bsz; i += 256) {
        int j = i >> 6, b = i & 63;
        pbs[j * Bsz + b] = g_pb[b * PBL + t + j];
    }
    __syncthreads();
    int gl = tid & 127, bh = tid >> 7;
    for (int bi = 0; bi < 32; bi++) {
        int b = bh * 32 + bi;
        float acc = 0.f;
#pragma unroll
        for (int j = 0; j < BCL; j++) {
            int v = pbs[j * Bsz + b];
            acc += g_PT[(size_t)(j * VOC + v) * G4 + g0 + gl];
        }
        os[gl * 65 + b] = acc;
    }
    __syncthreads();
    float* out = g_gx + (size_t)t * G4 * Bsz;
    for (int i = tid; i < 128 * Bsz; i += 256) {
        int row = i >> 6, b = i & 63;
        out[(size_t)(g0 + row) * Bsz + b] = os[row * 65 + b]
                                          + g_gctx0[(g0 + row) * Bsz + b];
    }
}

// ---------------- K4: fused two-layer recurrence (256 blocks) --------------
// Blocks 0..127: layer 0 (gx0-fed). Blocks 128..255: layer 1, lagging one
// step, consuming h1 hist chunks gated by layer 0's ck0 counters.
__global__ void __launch_bounds__(256, 2) k_fused(
    const float* __restrict__ Whh0, const float* __restrict__ Whh1,
    const float* __restrict__ Wih1, const float* __restrict__ bih1,
    const float* __restrict__ bhh1, const float* __restrict__ gx,
    float* __restrict__ h1hist, float* __restrict__ h2hist)
{
    extern __shared__ float dsm[];
    __shared__ __align__(16) float ex[Bsz * 16];
    float* W0  = dsm;                 // [16][WP]  Whh slice
    float* W1  = dsm + 16 * WP;       // [16][WP]  Wih slice (layer 1 only)
    float* hb0 = dsm + 32 * WP;
    float* hb1 = hb0 + 64 * HP;

    int tid = threadIdx.x, bid = blockIdx.x;
    bool l1 = bid >= GRIDR;
    int lb = l1 ? bid - GRIDR : bid;
    int j0 = lb * UPB;
    int mych = lb >> 4;

    for (int i = tid; i < 16 * HID; i += 256) {
        int lr = i >> 9, k = i & 511;
        int grow = ((lr & 3) << 9) + j0 + (lr >> 2);
        W0[lr * WP + k] = (l1 ? Whh1 : Whh0)[(size_t)grow * HID + k];
        if (l1) W1[lr * WP + k] = Wih1[(size_t)grow * HID + k];
    }

    int b = tid >> 2, q = tid & 3;
    const float* wp0[UPB];
    const float* wp1[UPB];
    float bias[UPB];
    size_t goff[UPB];
#pragma unroll
    for (int u = 0; u < UPB; u++) {
        int grow = (q << 9) + j0 + u;
        wp0[u] = W0 + (u * 4 + q) * WP;
        wp1[u] = W1 + (u * 4 + q) * WP;
        bias[u] = l1 ? (bih1[grow] + bhh1[grow]) : 0.f;
        goff[u] = (size_t)grow * Bsz + b;
    }
    StreamCtx sc;
#pragma unroll
    for (int n = 0; n < 4; n++) {
        int idx = tid + n * 256;
        sc.sb[n] = idx >> 4; sc.sk[n] = idx & 15;
        sc.sdst[0][n] = (uint32_t)__cvta_generic_to_shared(hb0 + sc.sb[n] * HP + sc.sk[n] * 4);
        sc.sdst[1][n] = (uint32_t)__cvta_generic_to_shared(hb1 + sc.sb[n] * HP + sc.sk[n] * 4);
    }
    float creg = 0.f;
    __syncthreads();

    for (int t = 0; t < Tlen; t++) {
        unsigned long long a0[UPB] = {0,0,0,0}, a1[UPB] = {0,0,0,0};
        float acc[UPB];
        if (!l1) {
            const float* gxt = gx + (size_t)t * G4 * Bsz;
#pragma unroll
            for (int u = 0; u < UPB; u++) acc[u] = __ldcg(gxt + goff[u]);
            if (t > 0)
                gemm_stream((const float4*)g_h0r[t & 1],
                            g_ck0 + (size_t)(t - 1) * NCH * CKS,
                            hb0, hb1, sc, wp0, b, tid, a0, a1);
        } else {
#pragma unroll
            for (int u = 0; u < UPB; u++) acc[u] = bias[u];
            if (t > 0)
                gemm_stream((const float4*)g_h1r[t & 1],
                            g_ck1 + (size_t)(t - 1) * NCH * CKS,
                            hb0, hb1, sc, wp0, b, tid, a0, a1);
            gemm_stream((const float4*)(h1hist + (size_t)t * Bsz * HID),
                        g_ck0 + (size_t)t * NCH * CKS,
                        hb0, hb1, sc, wp1, b, tid, a0, a1);
        }
#pragma unroll
        for (int u = 0; u < UPB; u++) acc[u] += usum(a0[u]) + usum(a1[u]);
#pragma unroll
        for (int u = 0; u < UPB; u++) ex[b * 16 + u * 4 + q] = acc[u];
        __syncthreads();
        {
            float4 g = *(const float4*)(ex + b * 16 + q * 4);
            float c = sigf(g.y) * creg + sigf(g.x) * tanh_fast(g.z);
            float h = sigf(g.w) * tanh_fast(c);
            creg = c;
            int j = j0 + q;
            float* ring = (l1 ? g_h1r : g_h0r)[(t + 1) & 1];
            float* hist = l1 ? h2hist : h1hist;
            ring[b * HID + j] = h;
            hist[((size_t)t * Bsz + b) * HID + j] = h;
        }
        __syncthreads();
        if (tid == 0)
            signal_chunk((l1 ? g_ck1 : g_ck0) + ((size_t)t * NCH + mych) * CKS);
    }
}

// ---------------- K5: output head ------------------------------------------
#define OW 516
__global__ void __launch_bounds__(256) k_out(const float* __restrict__ Wout,
                                             const float* __restrict__ bout,
                                             float* __restrict__ out) {
    extern __shared__ float dsm[];           // [64][OW]
    int vc = blockIdx.x;                     // 0..3
    int ts = blockIdx.y;                     // 0..31
    int tid = threadIdx.x;
    for (int i = tid; i < 64 * HID; i += 256) {
        int r = i >> 9, k = i & 511;
        dsm[r * OW + k] = Wout[(size_t)(vc * 64 + r) * HID + k];
    }
    __syncthreads();

    int b = tid >> 2, vg = tid & 3;
    float bo[16];
#pragma unroll
    for (int i = 0; i < 16; i++) bo[i] = bout[vc * 64 + vg + i * 4];

    for (int tt = 0; tt < 16; tt++) {
        int t = ts * 16 + tt;
        unsigned long long acc[16];
#pragma unroll
        for (int i = 0; i < 16; i++) acc[i] = 0ull;
        const ulonglong2* hp = (const ulonglong2*)(g_h2 + ((size_t)t * Bsz + b) * HID);
#pragma unroll 2
        for (int kc = 0; kc < 128; kc++) {
            ulonglong2 h4 = __ldcg(hp + kc);
            int k = kc * 4;
#pragma unroll
            for (int i = 0; i < 16; i++) {
                const ulonglong2 w4 =
                    *(const ulonglong2*)(dsm + (vg + i * 4) * OW + k);
                fma2(acc[i], h4.x, w4.x);
                fma2(acc[i], h4.y, w4.y);
            }
        }
#pragma unroll
        for (int i = 0; i < 16; i++) {
            int v = vc * 64 + vg + i * 4;
            out[((size_t)b * Tlen + t) * 256 + v] = usum(acc[i]) + bo[i];
        }
    }
}

// ---------------- launch ----------------------------------------------------
extern "C" void kernel_launch(void* const* d_in, const int* in_sizes, int n_in,
                              void* d_out, int out_size) {
    (void)in_sizes; (void)n_in; (void)out_size;
    const float* ecc  = (const float*)d_in[0];
    const int*   cat  = (const int*)  d_in[1];
    const float* num  = (const float*)d_in[2];
    const int*   pay  = (const int*)  d_in[3];
    const float* e0   = (const float*)d_in[4];
    const float* e1   = (const float*)d_in[5];
    const float* e2   = (const float*)d_in[6];
    const float* be   = (const float*)d_in[7];
    const float* Wih0 = (const float*)d_in[8];
    const float* Whh0 = (const float*)d_in[9];
    const float* bih0 = (const float*)d_in[10];
    const float* bhh0 = (const float*)d_in[11];
    const float* Wih1 = (const float*)d_in[12];
    const float* Whh1 = (const float*)d_in[13];
    const float* bih1 = (const float*)d_in[14];
    const float* bhh1 = (const float*)d_in[15];
    const float* Wout = (const float*)d_in[16];
    const float* bout = (const float*)d_in[17];
    float* out = (float*)d_out;

    float* gx;     cudaGetSymbolAddress((void**)&gx,  g_gx);
    float* h1;     cudaGetSymbolAddress((void**)&h1,  g_h1);
    float* h2;     cudaGetSymbolAddress((void**)&h2,  g_h2);
    unsigned* ck0; cudaGetSymbolAddress((void**)&ck0, g_ck0);
    unsigned* ck1; cudaGetSymbolAddress((void**)&ck1, g_ck1);

    const int SM_F   = (32 * WP + 2 * 64 * HP) * 4;   // 100,864 B -> 2 CTAs/SM
    const int SM_OUT = (64 * OW) * 4;                 // 132,096 B
    cudaFuncSetAttribute(k_fused, cudaFuncAttributeMaxDynamicSharedMemorySize, SM_F);
    cudaFuncSetAttribute(k_out,   cudaFuncAttributeMaxDynamicSharedMemorySize, SM_OUT);

    cudaMemsetAsync(ck0, 0, Tlen * NCH * CKS * sizeof(unsigned));
    cudaMemsetAsync(ck1, 0, Tlen * NCH * CKS * sizeof(unsigned));

    k_prep <<<Bsz, 128>>>(ecc, cat, num, pay, e0, e1, e2);
    k_gctx <<<G4, 64>>>(Wih0, bih0, bhh0);
    k_table<<<G4, 256>>>(Wih0, be);
    {
        dim3 gg(16, Tlen);
        k_gx0<<<gg, 256>>>();
    }
    k_fused<<<2 * GRIDR, 256, SM_F>>>(Whh0, Whh1, Wih1, bih1, bhh1, gx, h1, h2);
    {
        dim3 go(4, 32);
        k_out<<<go, 256, SM_OUT>>>(Wout, bout, out);
    }
}

// round 13
// speedup vs baseline: 1.3819x; 1.3819x over previous
#include <cuda_runtime.h>
#include <math.h>
#include <stdint.h>

#define Bsz   64
#define Tlen  512
#define HID   512
#define G4    2048
#define CTX   792
#define IND   1048
#define BCL   8
#define VOC   260
#define PBL   (Tlen + BCL)   // 520
#define PJ    (BCL * VOC)    // 2080
#define WP    516            // padded W row stride (mod 32 == 4 -> conflict-free)
#define HP2   132            // padded h-chunk row stride (128 + 4)
#define GRIDR 128
#define UPB   4              // hidden units per block
#define NCH   8              // producer signal chunks (64 units each)
#define KCH   4              // consumer k-chunks (128 k each)
#define CKS   32             // counter padding stride

// ---------------- device scratch ------------------------------------------
__device__ float g_ctxT[CTX * Bsz];
__device__ int   g_pb[Bsz * PBL];
__device__ float g_gctx0[G4 * Bsz];
__device__ float g_PT[(size_t)PJ * G4];
__device__ float g_gx[(size_t)Tlen * G4 * Bsz];       // gate preact [t][g][b]
__device__ float g_h[2][Bsz * HID];                   // h ring
__device__ float g_h1[(size_t)Tlen * Bsz * HID];      // layer-0 outputs [t][b][k]
__device__ float g_h2[(size_t)Tlen * Bsz * HID];      // layer-1 outputs
__device__ unsigned g_ck0[Tlen * NCH * CKS];
__device__ unsigned g_ck1[Tlen * NCH * CKS];

// ---------------- helpers --------------------------------------------------
__device__ __forceinline__ void fma2(unsigned long long& acc,
                                     unsigned long long a, unsigned long long b) {
    asm("fma.rn.f32x2 %0, %1, %2, %0;" : "+l"(acc) : "l"(a), "l"(b));
}
__device__ __forceinline__ float usum(unsigned long long v) {
    float lo = __uint_as_float((unsigned)(v & 0xffffffffull));
    float hi = __uint_as_float((unsigned)(v >> 32));
    return lo + hi;
}
__device__ __forceinline__ float sigf(float x) {
    return __fdividef(1.f, 1.f + __expf(-x));
}
__device__ __forceinline__ float tanh_fast(float x) {
    return __fmaf_rn(2.f, sigf(2.f * x), -1.f);
}
__device__ __forceinline__ void cpasync16(uint32_t s, const void* g) {
    asm volatile("cp.async.cg.shared.global [%0], [%1], 16;" :: "r"(s), "l"(g));
}
__device__ __forceinline__ void waitcnt16(const unsigned* p) {
    unsigned v;
    do {
        asm volatile("ld.acquire.gpu.global.u32 %0, [%1];" : "=r"(v) : "l"(p));
    } while (v < 16u);
}
__device__ __forceinline__ void signal_chunk(unsigned* p) {
    asm volatile("red.release.gpu.global.add.u32 [%0], %1;" :: "l"(p), "r"(1u) : "memory");
}

// ---------------- K0: context assembly (transposed) + byte stream ----------
__global__ void k_prep(const float* __restrict__ ecc, const int* __restrict__ cat,
                       const float* __restrict__ num, const int* __restrict__ pay,
                       const float* __restrict__ e0, const float* __restrict__ e1,
                       const float* __restrict__ e2) {
    int b = blockIdx.x;
    int c0 = cat[b * 3 + 0], c1 = cat[b * 3 + 1], c2 = cat[b * 3 + 2];
    for (int i = threadIdx.x; i < CTX; i += blockDim.x) {
        float v;
        if (i < 512)      v = ecc[b * 512 + i];
        else if (i < 562) v = e0[c0 * 50 + (i - 512)];
        else if (i < 626) v = e1[c1 * 64 + (i - 562)];
        else if (i < 776) v = e2[c2 * 150 + (i - 626)];
        else              v = num[b * 16 + (i - 776)];
        g_ctxT[i * Bsz + b] = v;
    }
    for (int p = threadIdx.x; p < PBL; p += blockDim.x) {
        int v = (p < BCL - 1) ? 256 : (p == BCL - 1 ? 257 : pay[b * Tlen + p - BCL]);
        g_pb[b * PBL + p] = v;
    }
}

// ---------------- K1: context gate projection ------------------------------
__global__ void k_gctx(const float* __restrict__ Wih0, const float* __restrict__ bih0,
                       const float* __restrict__ bhh0) {
    int g = blockIdx.x;
    int b = threadIdx.x;
    const float* w = Wih0 + (size_t)g * IND;
    float a0 = 0.f, a1 = 0.f, a2 = 0.f, a3 = 0.f;
    int k = 0;
    for (; k + 4 <= CTX; k += 4) {
        a0 += w[k]   * g_ctxT[k * Bsz + b];
        a1 += w[k+1] * g_ctxT[(k+1) * Bsz + b];
        a2 += w[k+2] * g_ctxT[(k+2) * Bsz + b];
        a3 += w[k+3] * g_ctxT[(k+3) * Bsz + b];
    }
    for (; k < CTX; k++) a0 += w[k] * g_ctxT[k * Bsz + b];
    g_gctx0[g * Bsz + b] = a0 + a1 + a2 + a3 + bih0[g] + bhh0[g];
}

// ---------------- K2: transposed byte-projection table ---------------------
__global__ void k_table(const float* __restrict__ Wih0, const float* __restrict__ be) {
    __shared__ float ws[BCL * 32];
    __shared__ float es[VOC * 33];
    int g = blockIdx.x, tid = threadIdx.x;
    if (tid < 256) ws[tid] = Wih0[(size_t)g * IND + CTX + tid];
    for (int i = tid; i < VOC * 32; i += blockDim.x) {
        int v = i >> 5, k = i & 31;
        es[v * 33 + k] = be[i];
    }
    __syncthreads();
    for (int idx = tid; idx < PJ; idx += blockDim.x) {
        int j = idx / VOC, v = idx - j * VOC;
        const float* w = ws + j * 32;
        const float* e = es + v * 33;
        float acc = 0.f;
#pragma unroll
        for (int k = 0; k < 32; k++) acc += w[k] * e[k];
        g_PT[(size_t)idx * G4 + g] = acc;
    }
}

// ---------------- K3: layer-0 input preactivation gx0[t][g][b] -------------
__global__ void __launch_bounds__(256) k_gx0() {
    __shared__ int pbs[BCL * Bsz];
    __shared__ float os[128 * 65];
    int g0 = blockIdx.x * 128;
    int t  = blockIdx.y;
    int tid = threadIdx.x;
    for (int i = tid; i < BCL * Bsz; i += 256) {
        int j = i >> 6, b = i & 63;
        pbs[j * Bsz + b] = g_pb[b * PBL + t + j];
    }
    __syncthreads();
    int gl = tid & 127, bh = tid >> 7;
    for (int bi = 0; bi < 32; bi++) {
        int b = bh * 32 + bi;
        float acc = 0.f;
#pragma unroll
        for (int j = 0; j < BCL; j++) {
            int v = pbs[j * Bsz + b];
            acc += g_PT[(size_t)(j * VOC + v) * G4 + g0 + gl];
        }
        os[gl * 65 + b] = acc;
    }
    __syncthreads();
    float* out = g_gx + (size_t)t * G4 * Bsz;
    for (int i = tid; i < 128 * Bsz; i += 256) {
        int row = i >> 6, b = i & 63;
        out[(size_t)(g0 + row) * Bsz + b] = os[row * 65 + b]
                                          + g_gctx0[(g0 + row) * Bsz + b];
    }
}

// ---------------- K4: recurrence — 512 threads, 4 k-chunks -----------------
// Thread (b = (tid>>2)&63, q = (tid&3) + 4*(tid>>8)) owns gate rows q, q+8.
// Warp = 8 b x 4 q -> W-LDS 1wf (4 consecutive rows), h-LDS 1wf.
__global__ void __launch_bounds__(512, 1) k_rec(const float* __restrict__ Whh,
                                                const float* __restrict__ gx,
                                                float* __restrict__ hist,
                                                unsigned* __restrict__ ck) {
    extern __shared__ float dsm[];
    float* Wsh = dsm;                            // [16][WP]
    float* hbuf[2] = { dsm + 16 * WP, dsm + 16 * WP + 64 * HP2 };
    __shared__ __align__(16) float ex[Bsz * 16];

    int tid = threadIdx.x, bid = blockIdx.x;
    int j0 = bid * UPB;
    int mych = bid >> 4;

    for (int i = tid; i < 16 * HID; i += 512) {
        int lr = i >> 9, k = i & 511;
        int grow = ((lr & 3) << 9) + j0 + (lr >> 2);  // lr = 4*unit + gate
        Wsh[lr * WP + k] = Whh[(size_t)grow * HID + k];
    }

    int b = (tid >> 2) & 63;
    int q = (tid & 3) + ((tid >> 8) << 2);       // 0..7
    int lr0 = q, lr1 = q + 8;
    const float* w0 = Wsh + lr0 * WP;
    const float* w1 = Wsh + lr1 * WP;
    size_t goff0 = (size_t)(((lr0 & 3) << 9) + j0 + (lr0 >> 2)) * Bsz + b;
    size_t goff1 = (size_t)(((lr1 & 3) << 9) + j0 + (lr1 >> 2)) * Bsz + b;

    // cp.async slots: 4 float4 per thread per chunk (2048 total = 32KB)
    int sb[4], sk[4];
    uint32_t sdst[2][4];
#pragma unroll
    for (int n = 0; n < 4; n++) {
        int idx = tid + n * 512;
        sb[n] = idx >> 5; sk[n] = idx & 31;
        sdst[0][n] = (uint32_t)__cvta_generic_to_shared(hbuf[0] + sb[n] * HP2 + sk[n] * 4);
        sdst[1][n] = (uint32_t)__cvta_generic_to_shared(hbuf[1] + sb[n] * HP2 + sk[n] * 4);
    }
    float creg = 0.f;                            // live in threads tid<256
    __syncthreads();

    for (int t = 0; t < Tlen; t++) {
        const float* gxt = gx + (size_t)t * G4 * Bsz;
        float acc0 = __ldcg(gxt + goff0);
        float acc1 = __ldcg(gxt + goff1);

        if (t > 0) {
            const float4* src = (const float4*)(g_h[t & 1]);
            const unsigned* ckt = ck + (size_t)(t - 1) * NCH * CKS;
            // prime chunk 0 (k-chunk c covers producer chunks 2c, 2c+1)
            if (tid == 0) { waitcnt16(ckt); waitcnt16(ckt + CKS); }
            __syncthreads();
#pragma unroll
            for (int n = 0; n < 4; n++)
                cpasync16(sdst[0][n], src + sb[n] * 128 + sk[n]);
            asm volatile("cp.async.commit_group;");

            unsigned long long a00 = 0, a01 = 0, a10 = 0, a11 = 0;
            for (int c = 0; c < KCH; c++) {
                if (c < KCH - 1) {
                    if (tid == 0) {
                        waitcnt16(ckt + (size_t)(2 * c + 2) * CKS);
                        waitcnt16(ckt + (size_t)(2 * c + 3) * CKS);
                    }
                    __syncthreads();            // prior compute on buf[(c+1)&1] done
                    int nb = (c + 1) & 1;
#pragma unroll
                    for (int n = 0; n < 4; n++)
                        cpasync16(sdst[nb][n], src + sb[n] * 128 + (c + 1) * 32 + sk[n]);
                    asm volatile("cp.async.commit_group;");
                    asm volatile("cp.async.wait_group 1;");
                } else {
                    asm volatile("cp.async.wait_group 0;");
                }
                __syncthreads();
                const float* hb = hbuf[c & 1] + b * HP2;
                const float* wc0 = w0 + c * 128;
                const float* wc1 = w1 + c * 128;
#pragma unroll 8
                for (int kk = 0; kk < 128; kk += 4) {
                    ulonglong2 h4 = *(const ulonglong2*)(hb + kk);
                    ulonglong2 x0 = *(const ulonglong2*)(wc0 + kk);
                    ulonglong2 x1 = *(const ulonglong2*)(wc1 + kk);
                    fma2(a00, h4.x, x0.x);
                    fma2(a01, h4.y, x0.y);
                    fma2(a10, h4.x, x1.x);
                    fma2(a11, h4.y, x1.y);
                }
            }
            acc0 += usum(a00) + usum(a01);
            acc1 += usum(a10) + usum(a11);
        }
        ex[b * 16 + lr0] = acc0;
        ex[b * 16 + lr1] = acc1;
        __syncthreads();
        if (tid < 256) {
            int cb = tid >> 2, cu = tid & 3;
            float4 g = *(const float4*)(ex + cb * 16 + cu * 4);
            float c = sigf(g.y) * creg + sigf(g.x) * tanh_fast(g.z);
            float h = sigf(g.w) * tanh_fast(c);
            creg = c;
            int j = j0 + cu;
            g_h[(t + 1) & 1][cb * HID + j] = h;
            hist[((size_t)t * Bsz + cb) * HID + j] = h;
        }
        __syncthreads();
        if (tid == 0) signal_chunk(ck + ((size_t)t * NCH + mych) * CKS);
    }
}

// ---------------- K5: gx1 = bias + W_ih1 @ h1[t]  (tiled fp32 GEMM) --------
__global__ void __launch_bounds__(256) k_gx1(const float* __restrict__ Wih,
                                             const float* __restrict__ bi1,
                                             const float* __restrict__ bh1) {
    __shared__ float As[64 * 64];
    __shared__ float Bs[64 * 64];
    int t = blockIdx.x, g0 = blockIdx.y * 64;
    int tid = threadIdx.x;
    int tg = tid >> 4, tb = tid & 15;

    unsigned long long acc[4][4];
#pragma unroll
    for (int u = 0; u < 4; u++)
#pragma unroll
        for (int i = 0; i < 4; i++) acc[u][i] = 0ull;

    const float* A = g_h1 + (size_t)t * Bsz * HID;
    const float* B = Wih + (size_t)g0 * HID;

    for (int kt = 0; kt < 8; kt++) {
        int k0 = kt * 64;
        __syncthreads();
#pragma unroll
        for (int n = 0; n < 4; n++) {
            int i = tid + n * 256;
            int row = i >> 4, c = i & 15;
            int cs = c ^ ((row >> 2) & 7);
            float4 va = *(const float4*)(A + row * HID + k0 + c * 4);
            float4 vb = *(const float4*)(B + (size_t)row * HID + k0 + c * 4);
            *(float4*)(As + row * 64 + cs * 4) = va;
            *(float4*)(Bs + row * 64 + cs * 4) = vb;
        }
        __syncthreads();
#pragma unroll
        for (int c = 0; c < 16; c++) {
            ulonglong2 h4[4], w4[4];
            int ca = (c ^ (tb & 7)) << 2;
            int cb = (c ^ (tg & 7)) << 2;
#pragma unroll
            for (int i = 0; i < 4; i++)
                h4[i] = *(const ulonglong2*)(As + (tb * 4 + i) * 64 + ca);
#pragma unroll
            for (int u = 0; u < 4; u++)
                w4[u] = *(const ulonglong2*)(Bs + (tg * 4 + u) * 64 + cb);
#pragma unroll
            for (int u = 0; u < 4; u++)
#pragma unroll
                for (int i = 0; i < 4; i++) {
                    fma2(acc[u][i], w4[u].x, h4[i].x);
                    fma2(acc[u][i], w4[u].y, h4[i].y);
                }
        }
    }
    float* out = g_gx + (size_t)t * G4 * Bsz;
#pragma unroll
    for (int u = 0; u < 4; u++) {
        int g = g0 + tg * 4 + u;
        float bias = bi1[g] + bh1[g];
        float4 r;
        r.x = usum(acc[u][0]) + bias;
        r.y = usum(acc[u][1]) + bias;
        r.z = usum(acc[u][2]) + bias;
        r.w = usum(acc[u][3]) + bias;
        *(float4*)(out + (size_t)g * Bsz + tb * 4) = r;
    }
}

// ---------------- K6: output head ------------------------------------------
#define OW 516
__global__ void __launch_bounds__(256) k_out(const float* __restrict__ Wout,
                                             const float* __restrict__ bout,
                                             float* __restrict__ out) {
    extern __shared__ float dsm[];           // [64][OW]
    int vc = blockIdx.x;                     // 0..3
    int ts = blockIdx.y;                     // 0..31
    int tid = threadIdx.x;
    for (int i = tid; i < 64 * HID; i += 256) {
        int r = i >> 9, k = i & 511;
        dsm[r * OW + k] = Wout[(size_t)(vc * 64 + r) * HID + k];
    }
    __syncthreads();

    int b = tid >> 2, vg = tid & 3;
    float bo[16];
#pragma unroll
    for (int i = 0; i < 16; i++) bo[i] = bout[vc * 64 + vg + i * 4];

    for (int tt = 0; tt < 16; tt++) {
        int t = ts * 16 + tt;
        unsigned long long acc[16];
#pragma unroll
        for (int i = 0; i < 16; i++) acc[i] = 0ull;
        const ulonglong2* hp = (const ulonglong2*)(g_h2 + ((size_t)t * Bsz + b) * HID);
#pragma unroll 2
        for (int kc = 0; kc < 128; kc++) {
            ulonglong2 h4 = __ldcg(hp + kc);
            int k = kc * 4;
#pragma unroll
            for (int i = 0; i < 16; i++) {
                const ulonglong2 w4 =
                    *(const ulonglong2*)(dsm + (vg + i * 4) * OW + k);
                fma2(acc[i], h4.x, w4.x);
                fma2(acc[i], h4.y, w4.y);
            }
        }
#pragma unroll
        for (int i = 0; i < 16; i++) {
            int v = vc * 64 + vg + i * 4;
            out[((size_t)b * Tlen + t) * 256 + v] = usum(acc[i]) + bo[i];
        }
    }
}

// ---------------- launch ----------------------------------------------------
extern "C" void kernel_launch(void* const* d_in, const int* in_sizes, int n_in,
                              void* d_out, int out_size) {
    (void)in_sizes; (void)n_in; (void)out_size;
    const float* ecc  = (const float*)d_in[0];
    const int*   cat  = (const int*)  d_in[1];
    const float* num  = (const float*)d_in[2];
    const int*   pay  = (const int*)  d_in[3];
    const float* e0   = (const float*)d_in[4];
    const float* e1   = (const float*)d_in[5];
    const float* e2   = (const float*)d_in[6];
    const float* be   = (const float*)d_in[7];
    const float* Wih0 = (const float*)d_in[8];
    const float* Whh0 = (const float*)d_in[9];
    const float* bih0 = (const float*)d_in[10];
    const float* bhh0 = (const float*)d_in[11];
    const float* Wih1 = (const float*)d_in[12];
    const float* Whh1 = (const float*)d_in[13];
    const float* bih1 = (const float*)d_in[14];
    const float* bhh1 = (const float*)d_in[15];
    const float* Wout = (const float*)d_in[16];
    const float* bout = (const float*)d_in[17];
    float* out = (float*)d_out;

    float* gx;     cudaGetSymbolAddress((void**)&gx,  g_gx);
    float* h1;     cudaGetSymbolAddress((void**)&h1,  g_h1);
    float* h2;     cudaGetSymbolAddress((void**)&h2,  g_h2);
    unsigned* ck0; cudaGetSymbolAddress((void**)&ck0, g_ck0);
    unsigned* ck1; cudaGetSymbolAddress((void**)&ck1, g_ck1);

    const int SM_REC = (16 * WP + 2 * 64 * HP2) * 4;  // 100,608 B
    const int SM_OUT = (64 * OW) * 4;                 // 132,096 B
    cudaFuncSetAttribute(k_rec, cudaFuncAttributeMaxDynamicSharedMemorySize, SM_REC);
    cudaFuncSetAttribute(k_out, cudaFuncAttributeMaxDynamicSharedMemorySize, SM_OUT);

    cudaMemsetAsync(ck0, 0, Tlen * NCH * CKS * sizeof(unsigned));
    cudaMemsetAsync(ck1, 0, Tlen * NCH * CKS * sizeof(unsigned));

    k_prep <<<Bsz, 128>>>(ecc, cat, num, pay, e0, e1, e2);
    k_gctx <<<G4, 64>>>(Wih0, bih0, bhh0);
    k_table<<<G4, 256>>>(Wih0, be);
    {
        dim3 gg(16, Tlen);
        k_gx0<<<gg, 256>>>();
    }
    k_rec  <<<GRIDR, 512, SM_REC>>>(Whh0, gx, h1, ck0);
    {
        dim3 gg(Tlen, 32);
        k_gx1<<<gg, 256>>>(Wih1, bih1, bhh1);
    }
    k_rec  <<<GRIDR, 512, SM_REC>>>(Whh1, gx, h2, ck1);
    {
        dim3 go(4, 32);
        k_out<<<go, 256, SM_OUT>>>(Wout, bout, out);
    }
}

// round 14
// speedup vs baseline: 1.5594x; 1.1284x over previous
#include <cuda_runtime.h>
#include <math.h>
#include <stdint.h>

#define Bsz   64
#define Tlen  512
#define HID   512
#define G4    2048
#define CTX   792
#define IND   1048
#define BCL   8
#define VOC   260
#define PBL   (Tlen + BCL)   // 520
#define PJ    (BCL * VOC)    // 2080
#define WP    516            // padded W row stride (mod 32 == 4 -> conflict-free)
#define HPB   260            // padded h-buffer row stride (256 + 4)
#define GRIDR 128
#define UPB   4              // hidden units per block
#define NCH   8              // producer signal chunks (64 units each)
#define CKS   32             // counter padding stride (128B per counter)

// ---------------- device scratch ------------------------------------------
__device__ float g_ctxT[CTX * Bsz];
__device__ int   g_pb[Bsz * PBL];
__device__ float g_gctx0[G4 * Bsz];
__device__ float g_PT[(size_t)PJ * G4];
__device__ float g_gx[(size_t)Tlen * G4 * Bsz];       // gate preact [t][g][b]
__device__ float g_h[2][Bsz * HID];                   // h ring
__device__ float g_h1[(size_t)Tlen * Bsz * HID];      // layer-0 outputs [t][b][k]
__device__ float g_h2[(size_t)Tlen * Bsz * HID];      // layer-1 outputs
__device__ unsigned g_ck0[Tlen * NCH * CKS];
__device__ unsigned g_ck1[Tlen * NCH * CKS];

// ---------------- helpers --------------------------------------------------
__device__ __forceinline__ void fma2(unsigned long long& acc,
                                     unsigned long long a, unsigned long long b) {
    asm("fma.rn.f32x2 %0, %1, %2, %0;" : "+l"(acc) : "l"(a), "l"(b));
}
__device__ __forceinline__ float usum(unsigned long long v) {
    float lo = __uint_as_float((unsigned)(v & 0xffffffffull));
    float hi = __uint_as_float((unsigned)(v >> 32));
    return lo + hi;
}
__device__ __forceinline__ float sigf(float x) {
    return __fdividef(1.f, 1.f + __expf(-x));
}
__device__ __forceinline__ float tanh_fast(float x) {
    return __fmaf_rn(2.f, sigf(2.f * x), -1.f);
}
__device__ __forceinline__ void cpasync16(uint32_t s, const void* g) {
    asm volatile("cp.async.cg.shared.global [%0], [%1], 16;" :: "r"(s), "l"(g));
}
__device__ __forceinline__ void waitcnt16(const unsigned* p) {
    unsigned v;
    do {
        asm volatile("ld.acquire.gpu.global.u32 %0, [%1];" : "=r"(v) : "l"(p));
    } while (v < 16u);
}
__device__ __forceinline__ void signal_chunk(unsigned* p) {
    asm volatile("red.release.gpu.global.add.u32 [%0], %1;" :: "l"(p), "r"(1u) : "memory");
}

// ---------------- K0: context assembly (transposed) + byte stream ----------
__global__ void k_prep(const float* __restrict__ ecc, const int* __restrict__ cat,
                       const float* __restrict__ num, const int* __restrict__ pay,
                       const float* __restrict__ e0, const float* __restrict__ e1,
                       const float* __restrict__ e2) {
    int b = blockIdx.x;
    int c0 = cat[b * 3 + 0], c1 = cat[b * 3 + 1], c2 = cat[b * 3 + 2];
    for (int i = threadIdx.x; i < CTX; i += blockDim.x) {
        float v;
        if (i < 512)      v = ecc[b * 512 + i];
        else if (i < 562) v = e0[c0 * 50 + (i - 512)];
        else if (i < 626) v = e1[c1 * 64 + (i - 562)];
        else if (i < 776) v = e2[c2 * 150 + (i - 626)];
        else              v = num[b * 16 + (i - 776)];
        g_ctxT[i * Bsz + b] = v;
    }
    for (int p = threadIdx.x; p < PBL; p += blockDim.x) {
        int v = (p < BCL - 1) ? 256 : (p == BCL - 1 ? 257 : pay[b * Tlen + p - BCL]);
        g_pb[b * PBL + p] = v;
    }
}

// ---------------- K1: fused ctx-projection + byte table --------------------
// Blocks 0..2047: gctx for g=bid. Blocks 2048..4095: table for g=bid-2048.
__global__ void __launch_bounds__(256) k_pre2(const float* __restrict__ Wih0,
                                              const float* __restrict__ bih0,
                                              const float* __restrict__ bhh0,
                                              const float* __restrict__ be) {
    int tid = threadIdx.x;
    if (blockIdx.x < 2048) {
        // ---- ctx projection: 256 threads = 64 b x 4 k-slices of 198 ----
        __shared__ float red[256];
        int g = blockIdx.x;
        int b = tid & 63, s = tid >> 6;
        const float* w = Wih0 + (size_t)g * IND;
        float a = 0.f;
        int k0 = s * 198, k1 = k0 + 198;
        for (int k = k0; k < k1; k++) a += w[k] * g_ctxT[k * Bsz + b];
        red[tid] = a;
        __syncthreads();
        if (tid < 64)
            g_gctx0[g * Bsz + tid] = red[tid] + red[tid + 64] + red[tid + 128]
                                   + red[tid + 192] + bih0[g] + bhh0[g];
    } else {
        // ---- byte-projection table for gate row g ----
        __shared__ float ws[BCL * 32];
        __shared__ float es[VOC * 33];
        int g = blockIdx.x - 2048;
        if (tid < 256) ws[tid] = Wih0[(size_t)g * IND + CTX + tid];
        for (int i = tid; i < VOC * 32; i += 256) {
            int v = i >> 5, k = i & 31;
            es[v * 33 + k] = be[i];
        }
        __syncthreads();
        for (int idx = tid; idx < PJ; idx += 256) {
            int j = idx / VOC, v = idx - j * VOC;
            const float* w = ws + j * 32;
            const float* e = es + v * 33;
            float acc = 0.f;
#pragma unroll
            for (int k = 0; k < 32; k++) acc += w[k] * e[k];
            g_PT[(size_t)idx * G4 + g] = acc;
        }
    }
}

// ---------------- K2: layer-0 input preactivation gx0[t][g][b] -------------
__global__ void __launch_bounds__(256) k_gx0() {
    __shared__ int pbs[BCL * Bsz];
    __shared__ float os[128 * 65];
    int g0 = blockIdx.x * 128;
    int t  = blockIdx.y;
    int tid = threadIdx.x;
    for (int i = tid; i < BCL * Bsz; i += 256) {
        int j = i >> 6, b = i & 63;
        pbs[j * Bsz + b] = g_pb[b * PBL + t + j];
    }
    __syncthreads();
    int gl = tid & 127, bh = tid >> 7;
    for (int bi = 0; bi < 32; bi++) {
        int b = bh * 32 + bi;
        float acc = 0.f;
#pragma unroll
        for (int j = 0; j < BCL; j++) {
            int v = pbs[j * Bsz + b];
            acc += g_PT[(size_t)(j * VOC + v) * G4 + g0 + gl];
        }
        os[gl * 65 + b] = acc;
    }
    __syncthreads();
    float* out = g_gx + (size_t)t * G4 * Bsz;
    for (int i = tid; i < 128 * Bsz; i += 256) {
        int row = i >> 6, b = i & 63;
        out[(size_t)(g0 + row) * Bsz + b] = os[row * 65 + b]
                                          + g_gctx0[(g0 + row) * Bsz + b];
    }
}

// ---------------- K3: recurrence — 2 fat half-h fetches per step -----------
// 512 threads; thread (b, q in 0..7) owns gate rows q, q+8.
__global__ void __launch_bounds__(512, 1) k_rec(const float* __restrict__ Whh,
                                                const float* __restrict__ gx,
                                                float* __restrict__ hist,
                                                unsigned* __restrict__ ck) {
    extern __shared__ float dsm[];
    float* Wsh = dsm;                                // [16][WP]
    float* hbuf0 = dsm + 16 * WP;                    // [64][HPB] (k 0..255)
    float* hbuf1 = hbuf0 + 64 * HPB;                 // [64][HPB] (k 256..511)
    __shared__ __align__(16) float ex[Bsz * 16];

    int tid = threadIdx.x, bid = blockIdx.x;
    int j0 = bid * UPB;
    int mych = bid >> 4;

    for (int i = tid; i < 16 * HID; i += 512) {
        int lr = i >> 9, k = i & 511;
        int grow = ((lr & 3) << 9) + j0 + (lr >> 2);
        Wsh[lr * WP + k] = Whh[(size_t)grow * HID + k];
    }

    int b = (tid >> 2) & 63;
    int q = (tid & 3) + ((tid >> 8) << 2);           // 0..7
    int lr0 = q, lr1 = q + 8;
    const float* w0 = Wsh + lr0 * WP;
    const float* w1 = Wsh + lr1 * WP;
    size_t goff0 = (size_t)(((lr0 & 3) << 9) + j0 + (lr0 >> 2)) * Bsz + b;
    size_t goff1 = (size_t)(((lr1 & 3) << 9) + j0 + (lr1 >> 2)) * Bsz + b;

    // staging slots: 8 float4 per thread per buffer
    int srow[8], scol[8];
    uint32_t sd0[8], sd1[8];
#pragma unroll
    for (int n = 0; n < 8; n++) {
        int idx = tid + n * 512;                     // 0..4095
        srow[n] = idx >> 6; scol[n] = idx & 63;
        sd0[n] = (uint32_t)__cvta_generic_to_shared(hbuf0 + srow[n] * HPB + scol[n] * 4);
        sd1[n] = (uint32_t)__cvta_generic_to_shared(hbuf1 + srow[n] * HPB + scol[n] * 4);
    }
    float creg = 0.f;                                // threads tid<256
    __syncthreads();

    for (int t = 0; t < Tlen; t++) {
        const float* gxt = gx + (size_t)t * G4 * Bsz;
        float acc0 = __ldcg(gxt + goff0);
        float acc1 = __ldcg(gxt + goff1);

        if (t > 0) {
            const float4* src = (const float4*)(g_h[t & 1]);
            const unsigned* ckt = ck + (size_t)(t - 1) * NCH * CKS;
            // fetch 0: k 0..255 (producer chunks 0..3), 4 parallel pollers
            if (tid < 4) waitcnt16(ckt + (size_t)tid * CKS);
            __syncthreads();
#pragma unroll
            for (int n = 0; n < 8; n++)
                cpasync16(sd0[n], src + srow[n] * 128 + scol[n]);
            asm volatile("cp.async.commit_group;");
            // fetch 1: k 256..511 (producer chunks 4..7)
            if (tid < 4) waitcnt16(ckt + (size_t)(4 + tid) * CKS);
            __syncthreads();
#pragma unroll
            for (int n = 0; n < 8; n++)
                cpasync16(sd1[n], src + srow[n] * 128 + 64 + scol[n]);
            asm volatile("cp.async.commit_group;");

            unsigned long long a00 = 0, a01 = 0, a10 = 0, a11 = 0;
            asm volatile("cp.async.wait_group 1;");
            __syncthreads();
            {
                const float* hb = hbuf0 + b * HPB;
#pragma unroll 8
                for (int kk = 0; kk < 256; kk += 4) {
                    ulonglong2 h4 = *(const ulonglong2*)(hb + kk);
                    ulonglong2 x0 = *(const ulonglong2*)(w0 + kk);
                    ulonglong2 x1 = *(const ulonglong2*)(w1 + kk);
                    fma2(a00, h4.x, x0.x);
                    fma2(a01, h4.y, x0.y);
                    fma2(a10, h4.x, x1.x);
                    fma2(a11, h4.y, x1.y);
                }
            }
            asm volatile("cp.async.wait_group 0;");
            __syncthreads();
            {
                const float* hb = hbuf1 + b * HPB;
                const float* wc0 = w0 + 256;
                const float* wc1 = w1 + 256;
#pragma unroll 8
                for (int kk = 0; kk < 256; kk += 4) {
                    ulonglong2 h4 = *(const ulonglong2*)(hb + kk);
                    ulonglong2 x0 = *(const ulonglong2*)(wc0 + kk);
                    ulonglong2 x1 = *(const ulonglong2*)(wc1 + kk);
                    fma2(a00, h4.x, x0.x);
                    fma2(a01, h4.y, x0.y);
                    fma2(a10, h4.x, x1.x);
                    fma2(a11, h4.y, x1.y);
                }
            }
            acc0 += usum(a00) + usum(a01);
            acc1 += usum(a10) + usum(a11);
        }
        ex[b * 16 + lr0] = acc0;
        ex[b * 16 + lr1] = acc1;
        __syncthreads();
        if (tid < 256) {
            int cb = tid >> 2, cu = tid & 3;
            float4 g = *(const float4*)(ex + cb * 16 + cu * 4);
            float c = sigf(g.y) * creg + sigf(g.x) * tanh_fast(g.z);
            float h = sigf(g.w) * tanh_fast(c);
            creg = c;
            int j = j0 + cu;
            g_h[(t + 1) & 1][cb * HID + j] = h;
            hist[((size_t)t * Bsz + cb) * HID + j] = h;
        }
        __syncthreads();
        if (tid == 0) signal_chunk(ck + ((size_t)t * NCH + mych) * CKS);
    }
}

// ---------------- K4: gx1 = bias + W_ih1 @ h1[t]  (tiled fp32 GEMM) --------
__global__ void __launch_bounds__(256) k_gx1(const float* __restrict__ Wih,
                                             const float* __restrict__ bi1,
                                             const float* __restrict__ bh1) {
    __shared__ float As[64 * 64];
    __shared__ float Bs[64 * 64];
    int t = blockIdx.x, g0 = blockIdx.y * 64;
    int tid = threadIdx.x;
    int tg = tid >> 4, tb = tid & 15;

    unsigned long long acc[4][4];
#pragma unroll
    for (int u = 0; u < 4; u++)
#pragma unroll
        for (int i = 0; i < 4; i++) acc[u][i] = 0ull;

    const float* A = g_h1 + (size_t)t * Bsz * HID;
    const float* B = Wih + (size_t)g0 * HID;

    for (int kt = 0; kt < 8; kt++) {
        int k0 = kt * 64;
        __syncthreads();
#pragma unroll
        for (int n = 0; n < 4; n++) {
            int i = tid + n * 256;
            int row = i >> 4, c = i & 15;
            int cs = c ^ ((row >> 2) & 7);
            float4 va = *(const float4*)(A + row * HID + k0 + c * 4);
            float4 vb = *(const float4*)(B + (size_t)row * HID + k0 + c * 4);
            *(float4*)(As + row * 64 + cs * 4) = va;
            *(float4*)(Bs + row * 64 + cs * 4) = vb;
        }
        __syncthreads();
#pragma unroll
        for (int c = 0; c < 16; c++) {
            ulonglong2 h4[4], w4[4];
            int ca = (c ^ (tb & 7)) << 2;
            int cb = (c ^ (tg & 7)) << 2;
#pragma unroll
            for (int i = 0; i < 4; i++)
                h4[i] = *(const ulonglong2*)(As + (tb * 4 + i) * 64 + ca);
#pragma unroll
            for (int u = 0; u < 4; u++)
                w4[u] = *(const ulonglong2*)(Bs + (tg * 4 + u) * 64 + cb);
#pragma unroll
            for (int u = 0; u < 4; u++)
#pragma unroll
                for (int i = 0; i < 4; i++) {
                    fma2(acc[u][i], w4[u].x, h4[i].x);
                    fma2(acc[u][i], w4[u].y, h4[i].y);
                }
        }
    }
    float* out = g_gx + (size_t)t * G4 * Bsz;
#pragma unroll
    for (int u = 0; u < 4; u++) {
        int g = g0 + tg * 4 + u;
        float bias = bi1[g] + bh1[g];
        float4 r;
        r.x = usum(acc[u][0]) + bias;
        r.y = usum(acc[u][1]) + bias;
        r.z = usum(acc[u][2]) + bias;
        r.w = usum(acc[u][3]) + bias;
        *(float4*)(out + (size_t)g * Bsz + tb * 4) = r;
    }
}

// ---------------- K5: output head ------------------------------------------
#define OW 516
__global__ void __launch_bounds__(256) k_out(const float* __restrict__ Wout,
                                             const float* __restrict__ bout,
                                             float* __restrict__ out) {
    extern __shared__ float dsm[];           // [64][OW]
    int vc = blockIdx.x;                     // 0..3
    int ts = blockIdx.y;                     // 0..31
    int tid = threadIdx.x;
    for (int i = tid; i < 64 * HID; i += 256) {
        int r = i >> 9, k = i & 511;
        dsm[r * OW + k] = Wout[(size_t)(vc * 64 + r) * HID + k];
    }
    __syncthreads();

    int b = tid >> 2, vg = tid & 3;
    float bo[16];
#pragma unroll
    for (int i = 0; i < 16; i++) bo[i] = bout[vc * 64 + vg + i * 4];

    for (int tt = 0; tt < 16; tt++) {
        int t = ts * 16 + tt;
        unsigned long long acc[16];
#pragma unroll
        for (int i = 0; i < 16; i++) acc[i] = 0ull;
        const ulonglong2* hp = (const ulonglong2*)(g_h2 + ((size_t)t * Bsz + b) * HID);
#pragma unroll 2
        for (int kc = 0; kc < 128; kc++) {
            ulonglong2 h4 = __ldcg(hp + kc);
            int k = kc * 4;
#pragma unroll
            for (int i = 0; i < 16; i++) {
                const ulonglong2 w4 =
                    *(const ulonglong2*)(dsm + (vg + i * 4) * OW + k);
                fma2(acc[i], h4.x, w4.x);
                fma2(acc[i], h4.y, w4.y);
            }
        }
#pragma unroll
        for (int i = 0; i < 16; i++) {
            int v = vc * 64 + vg + i * 4;
            out[((size_t)b * Tlen + t) * 256 + v] = usum(acc[i]) + bo[i];
        }
    }
}

// ---------------- launch ----------------------------------------------------
extern "C" void kernel_launch(void* const* d_in, const int* in_sizes, int n_in,
                              void* d_out, int out_size) {
    (void)in_sizes; (void)n_in; (void)out_size;
    const float* ecc  = (const float*)d_in[0];
    const int*   cat  = (const int*)  d_in[1];
    const float* num  = (const float*)d_in[2];
    const int*   pay  = (const int*)  d_in[3];
    const float* e0   = (const float*)d_in[4];
    const float* e1   = (const float*)d_in[5];
    const float* e2   = (const float*)d_in[6];
    const float* be   = (const float*)d_in[7];
    const float* Wih0 = (const float*)d_in[8];
    const float* Whh0 = (const float*)d_in[9];
    const float* bih0 = (const float*)d_in[10];
    const float* bhh0 = (const float*)d_in[11];
    const float* Wih1 = (const float*)d_in[12];
    const float* Whh1 = (const float*)d_in[13];
    const float* bih1 = (const float*)d_in[14];
    const float* bhh1 = (const float*)d_in[15];
    const float* Wout = (const float*)d_in[16];
    const float* bout = (const float*)d_in[17];
    float* out = (float*)d_out;

    float* gx;     cudaGetSymbolAddress((void**)&gx,  g_gx);
    float* h1;     cudaGetSymbolAddress((void**)&h1,  g_h1);
    float* h2;     cudaGetSymbolAddress((void**)&h2,  g_h2);
    unsigned* ck0; cudaGetSymbolAddress((void**)&ck0, g_ck0);
    unsigned* ck1; cudaGetSymbolAddress((void**)&ck1, g_ck1);

    const int SM_REC = (16 * WP + 2 * 64 * HPB) * 4;  // 166,144 B
    const int SM_OUT = (64 * OW) * 4;                 // 132,096 B
    cudaFuncSetAttribute(k_rec, cudaFuncAttributeMaxDynamicSharedMemorySize, SM_REC);
    cudaFuncSetAttribute(k_out, cudaFuncAttributeMaxDynamicSharedMemorySize, SM_OUT);

    cudaMemsetAsync(ck0, 0, Tlen * NCH * CKS * sizeof(unsigned));
    cudaMemsetAsync(ck1, 0, Tlen * NCH * CKS * sizeof(unsigned));

    k_prep <<<Bsz, 128>>>(ecc, cat, num, pay, e0, e1, e2);
    k_pre2 <<<4096, 256>>>(Wih0, bih0, bhh0, be);
    {
        dim3 gg(16, Tlen);
        k_gx0<<<gg, 256>>>();
    }
    k_rec  <<<GRIDR, 512, SM_REC>>>(Whh0, gx, h1, ck0);
    {
        dim3 gg(Tlen, 32);
        k_gx1<<<gg, 256>>>(Wih1, bih1, bhh1);
    }
    k_rec  <<<GRIDR, 512, SM_REC>>>(Whh1, gx, h2, ck1);
    {
        dim3 go(4, 32);
        k_out<<<go, 256, SM_OUT>>>(Wout, bout, out);
    }
}